// round 16
// baseline (speedup 1.0000x reference)
#include <cuda_runtime.h>
#include <cstdint>

#define KN 32
#define DF 128
#define RP 132   // DQ row pad: 132 mod 32 = 4 -> conflict-free frag/m-phase maps, 16B rows
#define LP 36    // L row pad: float2/float4 aligned, col reads conflict-free
#define GRID 740 // 5 CTAs/SM x 148 SMs (persistent)

// smem floats: DQ 64*RP=8448 | L 32*LP=1152 | stats 384 -> 39936 B, 5 CTAs/SM
#define SMEM_FLOATS (64 * RP + KN * LP + 384)
#define SMEM_BYTES  (SMEM_FLOATS * 4)

__device__ __forceinline__ unsigned bfpack(float e0, float e1) {
    unsigned r; asm("cvt.rn.bf16x2.f32 %0, %1, %2;" : "=r"(r) : "f"(e1), "f"(e0)); return r;
}
__device__ __forceinline__ void bfsplit(float e0, float e1, unsigned& hi, unsigned& lo) {
    hi = bfpack(e0, e1);
    float h0 = __uint_as_float(hi << 16);
    float h1 = __uint_as_float(hi & 0xFFFF0000u);
    lo = bfpack(e0 - h0, e1 - h1);
}
__device__ __forceinline__ void mma16(float* c, const unsigned* a, const unsigned* b) {
    asm volatile("mma.sync.aligned.m16n8k16.row.col.f32.bf16.bf16.f32 "
        "{%0,%1,%2,%3}, {%4,%5,%6,%7}, {%8,%9}, {%0,%1,%2,%3};"
        : "+f"(c[0]), "+f"(c[1]), "+f"(c[2]), "+f"(c[3])
        : "r"(a[0]), "r"(a[1]), "r"(a[2]), "r"(a[3]), "r"(b[0]), "r"(b[1]));
}
__device__ __forceinline__ void cpa16(uint32_t dst, const float* src) {
    asm volatile("cp.async.cg.shared.global [%0], [%1], 16;" :: "r"(dst), "l"(src));
}
__device__ __forceinline__ int load_idx(const int* __restrict__ sim,
                                        const int* __restrict__ cor,
                                        size_t node, int q, int lane) {
    int r = 0;
    const int gr = 16 * q + (lane & 15);
    if (lane < 16)
        r = (gr < KN) ? __ldg(sim + node * KN + gr)
                      : __ldg(cor + node * KN + gr - KN);
    return r;
}
__device__ __forceinline__ void issue_gather(float* DQ, const float* __restrict__ feat,
                                             int rowidx, int lane, int q) {
    const int jg = lane >> 3;
    const int c8 = lane & 7;
    #pragma unroll
    for (int it = 0; it < 4; it++) {
        const int rloc = 4 * it + jg;
        const int ridx = __shfl_sync(0xffffffffu, rowidx, rloc);
        const int r    = 16 * q + rloc;
        const float* src = feat + (size_t)ridx * DF;
        uint32_t dst = (uint32_t)__cvta_generic_to_shared(DQ + r * RP);
        #pragma unroll
        for (int dc = 0; dc < 4; dc++) {
            const int c4i = dc * 8 + c8;
            cpa16(dst + 16 * c4i, src + 4 * c4i);
        }
    }
    asm volatile("cp.async.commit_group;");
}

__global__ void __launch_bounds__(128, 5)
coatt_mma(const float* __restrict__ feat,
          const int* __restrict__ sim_idx,
          const int* __restrict__ cor_idx,
          float* __restrict__ out,
          int n_nodes)
{
    extern __shared__ float sh[];
    float* DQ    = sh;                     // [64][RP] rows 0-31 Dm, 32-63 Qm
    float* L     = sh + 64 * RP;           // [32][LP]; later sm[384]
    float* stats = L + KN * LP;
    float* Mc = stats;                     // col max   -> later Wv
    float* Ci = stats + 32;                // 1/(32*colsum) -> later Pv
    float* Mr = stats + 64;                // row max   -> later Vv
    float* Rs = stats + 96;                // row sum
    float* Wp = stats + 128;               // [4][32] w partials
    float* Vp = stats + 256;               // [4][32] v partials
    float* sm = L;                         // alias: written after L dead

    const int tid  = threadIdx.x;
    const int q    = tid >> 5;
    const int lane = tid & 31;
    const int nh   = q >> 1;               // n-half: cols [16nh, 16nh+16)
    const int dh   = q & 1;                // d-half: k in [64dh, 64dh+64)

    size_t node = blockIdx.x;
    if (node >= (size_t)n_nodes) return;

    // ---- prologue: first node's indices + residual + gather ----
    {
        int ri = load_idx(sim_idx, cor_idx, node, q, lane);
        issue_gather(DQ, feat, ri, lane, q);
    }
    float res = __ldg(feat + node * DF + tid);

    for (;;) {
        const size_t next = node + GRID;
        const bool has_next = next < (size_t)n_nodes;
        const size_t ncl = has_next ? next : node;
        // prefetch next node's indices + residual (latency hidden by compute)
        const int rowidx_n = load_idx(sim_idx, cor_idx, ncl, q, lane);
        const float res_n  = __ldg(feat + ncl * DF + tid);

        asm volatile("cp.async.wait_group 0;");
        __syncthreads();

        // ---- L tile via split-bf16 3-term mma: warp q = (nh, dh) ----
        float C[2][2][4];
        #pragma unroll
        for (int mi = 0; mi < 2; mi++)
            #pragma unroll
            for (int ni = 0; ni < 2; ni++)
                #pragma unroll
                for (int e = 0; e < 4; e++) C[mi][ni][e] = 0.f;

        const int r8 = lane >> 2;
        const int c4 = lane & 3;
        #pragma unroll
        for (int kt = 0; kt < 4; kt++) {
            const int d0 = 64 * dh + 16 * kt;
            unsigned ah[2][4], al[2][4];
            #pragma unroll
            for (int mi = 0; mi < 2; mi++) {
                const float* base = DQ + (16 * mi + r8) * RP + d0 + 2 * c4;
                float2 p0 = *(const float2*)(base);
                float2 p1 = *(const float2*)(base + 8 * RP);
                float2 p2 = *(const float2*)(base + 8);
                float2 p3 = *(const float2*)(base + 8 * RP + 8);
                bfsplit(p0.x, p0.y, ah[mi][0], al[mi][0]);
                bfsplit(p1.x, p1.y, ah[mi][1], al[mi][1]);
                bfsplit(p2.x, p2.y, ah[mi][2], al[mi][2]);
                bfsplit(p3.x, p3.y, ah[mi][3], al[mi][3]);
            }
            unsigned bh[2][2], bl[2][2];
            #pragma unroll
            for (int ni = 0; ni < 2; ni++) {
                const float* base = DQ + (32 + 16 * nh + 8 * ni + r8) * RP + d0 + 2 * c4;
                float2 p0 = *(const float2*)(base);
                float2 p1 = *(const float2*)(base + 8);
                bfsplit(p0.x, p0.y, bh[ni][0], bl[ni][0]);
                bfsplit(p1.x, p1.y, bh[ni][1], bl[ni][1]);
            }
            #pragma unroll
            for (int mi = 0; mi < 2; mi++)
                #pragma unroll
                for (int ni = 0; ni < 2; ni++) {
                    mma16(C[mi][ni], al[mi], bh[ni]);
                    mma16(C[mi][ni], ah[mi], bl[ni]);
                    mma16(C[mi][ni], ah[mi], bh[ni]);
                }
        }

        // ---- merge d-halves: dh0 stores, dh1 adds ----
        if (dh == 0) {
            #pragma unroll
            for (int mi = 0; mi < 2; mi++)
                #pragma unroll
                for (int ni = 0; ni < 2; ni++) {
                    const int row = 16 * mi + r8;
                    const int col = 16 * nh + 8 * ni + 2 * c4;
                    *(float2*)(L + row * LP + col)       = make_float2(C[mi][ni][0], C[mi][ni][1]);
                    *(float2*)(L + (row + 8) * LP + col) = make_float2(C[mi][ni][2], C[mi][ni][3]);
                }
        }
        __syncthreads();
        if (dh == 1) {
            #pragma unroll
            for (int mi = 0; mi < 2; mi++)
                #pragma unroll
                for (int ni = 0; ni < 2; ni++) {
                    const int row = 16 * mi + r8;
                    const int col = 16 * nh + 8 * ni + 2 * c4;
                    float2 t0 = *(float2*)(L + row * LP + col);
                    float2 t1 = *(float2*)(L + (row + 8) * LP + col);
                    t0.x += C[mi][ni][0]; t0.y += C[mi][ni][1];
                    t1.x += C[mi][ni][2]; t1.y += C[mi][ni][3];
                    *(float2*)(L + row * LP + col)       = t0;
                    *(float2*)(L + (row + 8) * LP + col) = t1;
                }
        }
        __syncthreads();

        // ---- stats: warp0 col max/sum (scalar), warp1 row max/sum (rotated float4) ----
        if (q == 0) {
            const int j = lane;
            float mc = -1e30f;
            #pragma unroll
            for (int k = 0; k < KN; k++) mc = fmaxf(mc, L[k * LP + j]);
            float cs = 0.f;
            #pragma unroll
            for (int k = 0; k < KN; k++) cs += __expf(L[k * LP + j] - mc);
            Mc[j] = mc;
            Ci[j] = 1.0f / (32.0f * cs);
        } else if (q == 1) {
            const int k = lane;
            const float* ra = L + k * LP;
            float mr = -1e30f;
            #pragma unroll
            for (int i = 0; i < 8; i++) {
                const int cc = 4 * ((i + (k >> 3)) & 7);
                float4 v = *(const float4*)(ra + cc);
                mr = fmaxf(mr, fmaxf(fmaxf(v.x, v.y), fmaxf(v.z, v.w)));
            }
            float rs = 0.f;
            #pragma unroll
            for (int i = 0; i < 8; i++) {
                const int cc = 4 * ((i + (k >> 3)) & 7);
                float4 v = *(const float4*)(ra + cc);
                rs += __expf(v.x - mr) + __expf(v.y - mr) + __expf(v.z - mr) + __expf(v.w - mr);
            }
            Mr[k] = mr;
            Rs[k] = rs;
        }
        __syncthreads();

        // ---- w partials: all 4 warps, rotated k-chunk ----
        {
            const int j  = lane;
            const int k0 = 8 * ((q + (j >> 3)) & 3);
            const float* pa = L + j * LP + k0;
            float4 a0 = *(const float4*)pa;
            float4 a1 = *(const float4*)(pa + 4);
            float wj;
            wj  = __expf(a0.x - Mc[k0 + 0]) * Ci[k0 + 0];
            wj += __expf(a0.y - Mc[k0 + 1]) * Ci[k0 + 1];
            wj += __expf(a0.z - Mc[k0 + 2]) * Ci[k0 + 2];
            wj += __expf(a0.w - Mc[k0 + 3]) * Ci[k0 + 3];
            wj += __expf(a1.x - Mc[k0 + 4]) * Ci[k0 + 4];
            wj += __expf(a1.y - Mc[k0 + 5]) * Ci[k0 + 5];
            wj += __expf(a1.z - Mc[k0 + 6]) * Ci[k0 + 6];
            wj += __expf(a1.w - Mc[k0 + 7]) * Ci[k0 + 7];
            Wp[q * 32 + j] = wj;
        }
        __syncthreads();

        // ---- Wv/Pv reduce (warp0) ----
        if (tid < 32) {
            const int j = tid;
            float wv = (Wp[j] + Wp[32 + j]) + (Wp[64 + j] + Wp[96 + j]);
            Mc[j] = wv;                        // Wv
            Ci[j] = __fdividef(wv, Rs[j]);     // Pv
        }
        __syncthreads();

        // ---- v partials: warp q, k in [8q,8q+8), column reads ----
        {
            const int j = lane;
            float vj = 0.f;
            #pragma unroll
            for (int i = 0; i < 8; i++) {
                const int k = 8 * q + i;
                vj += Ci[k] * __expf(L[k * LP + j] - Mr[k]);
            }
            Vp[q * 32 + j] = vj;
        }
        __syncthreads();

        // ---- Vv reduce (warp0) into Mr ----
        if (tid < 32) {
            const int j = tid;
            Mr[j] = (Vp[j] + Vp[32 + j]) + (Vp[64 + j] + Vp[96 + j]);   // Vv
        }
        __syncthreads();

        // ---- m = [mean_k Qm | w^T Dm | v^T Qm] (last DQ reader) ----
        {
            const int d = tid;
            float m1 = 0.f, m2 = 0.f, m3 = 0.f;
            #pragma unroll
            for (int j = 0; j < KN; j++) {
                float dd = DQ[j * RP + d];
                float qq = DQ[(32 + j) * RP + d];
                m1 += qq;
                m2 += Mc[j] * dd;     // Wv
                m3 += Mr[j] * qq;     // Vv
            }
            sm[d]       = m1 * (1.0f / 32.0f);
            sm[128 + d] = m2;
            sm[256 + d] = m3;
        }
        __syncthreads();

        // ---- DQ is dead: overlap next node's gather with epilogue ----
        if (has_next)
            issue_gather(DQ, feat, rowidx_n, lane, q);

        // ---- AvgPool1d(3,3) + residual ----
        {
            const int g = tid;
            float h = (sm[3 * g] + sm[3 * g + 1] + sm[3 * g + 2]) * (1.0f / 3.0f);
            out[node * DF + g] = res + h;
        }

        if (!has_next) break;
        res  = res_n;
        node = next;
    }
}

extern "C" void kernel_launch(void* const* d_in, const int* in_sizes, int n_in,
                              void* d_out, int out_size)
{
    const float* feat = (const float*)d_in[0];
    const int*   sim  = (const int*)d_in[1];
    const int*   cor  = (const int*)d_in[2];
    float*       out  = (float*)d_out;

    const int n_nodes = in_sizes[1] / KN;    // 20000
    const int grid = (n_nodes < GRID) ? n_nodes : GRID;
    cudaFuncSetAttribute(coatt_mma, cudaFuncAttributeMaxDynamicSharedMemorySize, SMEM_BYTES);
    coatt_mma<<<grid, 128, SMEM_BYTES>>>(feat, sim, cor, out, n_nodes);
}

// round 17
// speedup vs baseline: 1.2616x; 1.2616x over previous
#include <cuda_runtime.h>
#include <cstdint>

#define KN 32
#define DF 128
#define RP 132   // DQ row pad: 132 mod 32 = 4 -> conflict-free frag/m-phase maps, 16B rows
#define LP 36    // L row pad: float2/float4 aligned, col reads conflict-free

// smem floats: DQ 64*RP=8448 | L 32*LP=1152 | stats 384  -> 39936 B, 5 CTAs/SM
#define SMEM_FLOATS (64 * RP + KN * LP + 384)
#define SMEM_BYTES  (SMEM_FLOATS * 4)

// pack two f32 into bf16x2 (e0 -> low half, e1 -> high half)
__device__ __forceinline__ unsigned bfpack(float e0, float e1) {
    unsigned r; asm("cvt.rn.bf16x2.f32 %0, %1, %2;" : "=r"(r) : "f"(e1), "f"(e0)); return r;
}
// split f32 pair into (hi bf16x2, lo bf16x2)
__device__ __forceinline__ void bfsplit(float e0, float e1, unsigned& hi, unsigned& lo) {
    hi = bfpack(e0, e1);
    float h0 = __uint_as_float(hi << 16);
    float h1 = __uint_as_float(hi & 0xFFFF0000u);
    lo = bfpack(e0 - h0, e1 - h1);
}
__device__ __forceinline__ void mma16(float* c, const unsigned* a, const unsigned* b) {
    asm volatile("mma.sync.aligned.m16n8k16.row.col.f32.bf16.bf16.f32 "
        "{%0,%1,%2,%3}, {%4,%5,%6,%7}, {%8,%9}, {%0,%1,%2,%3};"
        : "+f"(c[0]), "+f"(c[1]), "+f"(c[2]), "+f"(c[3])
        : "r"(a[0]), "r"(a[1]), "r"(a[2]), "r"(a[3]), "r"(b[0]), "r"(b[1]));
}
__device__ __forceinline__ void cpa16(uint32_t dst, const float* src) {
    asm volatile("cp.async.cg.shared.global [%0], [%1], 16;" :: "r"(dst), "l"(src));
}

__global__ void __launch_bounds__(128, 5)
coatt_mma(const float* __restrict__ feat,
          const int* __restrict__ sim_idx,
          const int* __restrict__ cor_idx,
          float* __restrict__ out)
{
    extern __shared__ float sh[];
    float* DQ    = sh;                     // [64][RP] rows 0-31 Dm, 32-63 Qm
    float* L     = sh + 64 * RP;           // [32][LP] single L buffer
    float* stats = L + KN * LP;
    float* Mc = stats;                     // col max      -> later Wv
    float* Ci = stats + 32;                // 1/(32*csum)  -> later Pv
    float* Mr = stats + 64;                // row max      -> later Vv
    float* Rs = stats + 96;                // row sum
    float* Wp = stats + 128;               // [4][32] w partials
    float* Vp = stats + 256;               // [4][32] v partials
    float* sm = L;                         // alias: written after L dead

    const int tid  = threadIdx.x;
    const int q    = tid >> 5;
    const int lane = tid & 31;
    const int nh   = q >> 1;               // n-half: cols [16nh, 16nh+16)
    const int dh   = q & 1;                // d-half: d in [64dh, 64dh+64)
    const size_t node = blockIdx.x;

    // ---- early residual prefetch (hides tail LDG) ----
    const float res = __ldg(feat + node * DF + tid);

    // ---- neighbor indices via LDG + shfl ----
    int rowidx = 0;
    {
        const int gr = 16 * q + (lane & 15);
        if (lane < 16)
            rowidx = (gr < KN) ? __ldg(sim_idx + node * KN + gr)
                               : __ldg(cor_idx + node * KN + gr - KN);
    }

    // ---- gather via cp.async: warp q fills rows [16q,16q+16) ----
    {
        const int jg = lane >> 3;
        const int c8 = lane & 7;
        #pragma unroll
        for (int it = 0; it < 4; it++) {
            const int rloc = 4 * it + jg;
            const int ridx = __shfl_sync(0xffffffffu, rowidx, rloc);
            const int r    = 16 * q + rloc;
            const float* src = feat + (size_t)ridx * DF;
            uint32_t dst = (uint32_t)__cvta_generic_to_shared(DQ + r * RP);
            #pragma unroll
            for (int dc = 0; dc < 4; dc++) {
                const int c4 = dc * 8 + c8;
                cpa16(dst + 16 * c4, src + 4 * c4);
            }
        }
        asm volatile("cp.async.commit_group;");
        asm volatile("cp.async.wait_group 0;");
    }
    __syncthreads();

    // ---- L tile via split-bf16 3-term mma: warp q = (n-half nh, d-half dh) ----
    float C[2][2][4];
    #pragma unroll
    for (int mi = 0; mi < 2; mi++)
        #pragma unroll
        for (int ni = 0; ni < 2; ni++)
            #pragma unroll
            for (int e = 0; e < 4; e++) C[mi][ni][e] = 0.f;

    const int r8 = lane >> 2;              // 0..7
    const int c4 = lane & 3;               // 0..3
    #pragma unroll
    for (int kt = 0; kt < 4; kt++) {
        const int d0 = 64 * dh + 16 * kt;
        unsigned ah[2][4], al[2][4];
        #pragma unroll
        for (int mi = 0; mi < 2; mi++) {
            const float* base = DQ + (16 * mi + r8) * RP + d0 + 2 * c4;
            float2 p0 = *(const float2*)(base);
            float2 p1 = *(const float2*)(base + 8 * RP);
            float2 p2 = *(const float2*)(base + 8);
            float2 p3 = *(const float2*)(base + 8 * RP + 8);
            bfsplit(p0.x, p0.y, ah[mi][0], al[mi][0]);
            bfsplit(p1.x, p1.y, ah[mi][1], al[mi][1]);
            bfsplit(p2.x, p2.y, ah[mi][2], al[mi][2]);
            bfsplit(p3.x, p3.y, ah[mi][3], al[mi][3]);
        }
        unsigned bh[2][2], bl[2][2];
        #pragma unroll
        for (int ni = 0; ni < 2; ni++) {
            const float* base = DQ + (32 + 16 * nh + 8 * ni + r8) * RP + d0 + 2 * c4;
            float2 p0 = *(const float2*)(base);
            float2 p1 = *(const float2*)(base + 8);
            bfsplit(p0.x, p0.y, bh[ni][0], bl[ni][0]);
            bfsplit(p1.x, p1.y, bh[ni][1], bl[ni][1]);
        }
        #pragma unroll
        for (int mi = 0; mi < 2; mi++)
            #pragma unroll
            for (int ni = 0; ni < 2; ni++) {
                mma16(C[mi][ni], al[mi], bh[ni]);
                mma16(C[mi][ni], ah[mi], bl[ni]);
                mma16(C[mi][ni], ah[mi], bh[ni]);
            }
    }

    // ---- merge d-halves: dh0 stores, dh1 adds (disjoint n-halves concurrent) ----
    if (dh == 0) {
        #pragma unroll
        for (int mi = 0; mi < 2; mi++)
            #pragma unroll
            for (int ni = 0; ni < 2; ni++) {
                const int row = 16 * mi + r8;
                const int col = 16 * nh + 8 * ni + 2 * c4;
                *(float2*)(L + row * LP + col)       = make_float2(C[mi][ni][0], C[mi][ni][1]);
                *(float2*)(L + (row + 8) * LP + col) = make_float2(C[mi][ni][2], C[mi][ni][3]);
            }
    }
    __syncthreads();
    if (dh == 1) {
        #pragma unroll
        for (int mi = 0; mi < 2; mi++)
            #pragma unroll
            for (int ni = 0; ni < 2; ni++) {
                const int row = 16 * mi + r8;
                const int col = 16 * nh + 8 * ni + 2 * c4;
                float2 t0 = *(float2*)(L + row * LP + col);
                float2 t1 = *(float2*)(L + (row + 8) * LP + col);
                t0.x += C[mi][ni][0]; t0.y += C[mi][ni][1];
                t1.x += C[mi][ni][2]; t1.y += C[mi][ni][3];
                *(float2*)(L + row * LP + col)       = t0;
                *(float2*)(L + (row + 8) * LP + col) = t1;
            }
    }
    __syncthreads();

    // ---- stats: warp0 col max/sum (scalar, conflict-free), warp1 row (rotated float4) ----
    if (q == 0) {
        const int j = lane;
        float mc = -1e30f;
        #pragma unroll
        for (int k = 0; k < KN; k++) mc = fmaxf(mc, L[k * LP + j]);
        float cs = 0.f;
        #pragma unroll
        for (int k = 0; k < KN; k++) cs += __expf(L[k * LP + j] - mc);
        Mc[j] = mc;
        Ci[j] = 1.0f / (32.0f * cs);
    } else if (q == 1) {
        const int k = lane;
        const float* ra = L + k * LP;
        float mr = -1e30f;
        #pragma unroll
        for (int i = 0; i < 8; i++) {
            const int cc = 4 * ((i + (k >> 3)) & 7);
            float4 v = *(const float4*)(ra + cc);
            mr = fmaxf(mr, fmaxf(fmaxf(v.x, v.y), fmaxf(v.z, v.w)));
        }
        float rs = 0.f;
        #pragma unroll
        for (int i = 0; i < 8; i++) {
            const int cc = 4 * ((i + (k >> 3)) & 7);
            float4 v = *(const float4*)(ra + cc);
            rs += __expf(v.x - mr) + __expf(v.y - mr) + __expf(v.z - mr) + __expf(v.w - mr);
        }
        Mr[k] = mr;
        Rs[k] = rs;
    }
    __syncthreads();

    // ---- w partials: all 4 warps, rotated k-chunk (conflict-free rows) ----
    {
        const int j  = lane;
        const int k0 = 8 * ((q + (j >> 3)) & 3);
        const float* pa = L + j * LP + k0;
        float4 a0 = *(const float4*)pa;
        float4 a1 = *(const float4*)(pa + 4);
        float wj;
        wj  = __expf(a0.x - Mc[k0 + 0]) * Ci[k0 + 0];
        wj += __expf(a0.y - Mc[k0 + 1]) * Ci[k0 + 1];
        wj += __expf(a0.z - Mc[k0 + 2]) * Ci[k0 + 2];
        wj += __expf(a0.w - Mc[k0 + 3]) * Ci[k0 + 3];
        wj += __expf(a1.x - Mc[k0 + 4]) * Ci[k0 + 4];
        wj += __expf(a1.y - Mc[k0 + 5]) * Ci[k0 + 5];
        wj += __expf(a1.z - Mc[k0 + 6]) * Ci[k0 + 6];
        wj += __expf(a1.w - Mc[k0 + 7]) * Ci[k0 + 7];
        Wp[q * 32 + j] = wj;
    }
    __syncthreads();

    // ---- Wv/Pv reduce (warp0); Mc/Ci dead after w phase ----
    if (tid < 32) {
        const int j = tid;
        float wv = (Wp[j] + Wp[32 + j]) + (Wp[64 + j] + Wp[96 + j]);
        Mc[j] = wv;                        // Wv
        Ci[j] = __fdividef(wv, Rs[j]);     // Pv
    }
    __syncthreads();

    // ---- v partials: warp q, k in [8q,8q+8), column reads (conflict-free) ----
    {
        const int j = lane;
        float vj = 0.f;
        #pragma unroll
        for (int i = 0; i < 8; i++) {
            const int k = 8 * q + i;
            vj += Ci[k] * __expf(L[k * LP + j] - Mr[k]);
        }
        Vp[q * 32 + j] = vj;
    }
    __syncthreads();

    // ---- Vv reduce (warp0) into Mr (dead) ----
    if (tid < 32) {
        const int j = tid;
        Mr[j] = (Vp[j] + Vp[32 + j]) + (Vp[64 + j] + Vp[96 + j]);   // Vv
    }
    __syncthreads();

    // ---- m = [mean_k Qm | w^T Dm | v^T Qm] (bank 4j+d, lanes distinct) ----
    {
        const int d = tid;
        float m1 = 0.f, m2 = 0.f, m3 = 0.f;
        #pragma unroll
        for (int j = 0; j < KN; j++) {
            float dd = DQ[j * RP + d];
            float qq = DQ[(32 + j) * RP + d];
            m1 += qq;
            m2 += Mc[j] * dd;     // Wv
            m3 += Mr[j] * qq;     // Vv
        }
        sm[d]       = m1 * (1.0f / 32.0f);
        sm[128 + d] = m2;
        sm[256 + d] = m3;
    }
    __syncthreads();

    // ---- AvgPool1d(3,3) + residual (prefetched) ----
    {
        const int g = tid;
        float h = (sm[3 * g] + sm[3 * g + 1] + sm[3 * g + 2]) * (1.0f / 3.0f);
        out[node * DF + g] = res + h;
    }
}

extern "C" void kernel_launch(void* const* d_in, const int* in_sizes, int n_in,
                              void* d_out, int out_size)
{
    const float* feat = (const float*)d_in[0];
    const int*   sim  = (const int*)d_in[1];
    const int*   cor  = (const int*)d_in[2];
    float*       out  = (float*)d_out;

    const int n_nodes = in_sizes[1] / KN;    // 20000
    cudaFuncSetAttribute(coatt_mma, cudaFuncAttributeMaxDynamicSharedMemorySize, SMEM_BYTES);
    coatt_mma<<<n_nodes, 128, SMEM_BYTES>>>(feat, sim, cor, out);
}